// round 5
// baseline (speedup 1.0000x reference)
#include <cuda_runtime.h>
#include <mma.h>
using namespace nvcuda;

#define BB 2
#define SS 2048
#define HH 768
#define NH 12
#define DD 64
#define BH (BB*NH)                 // 24
#define M_PROJ (BB*SS)             // 4096
#define OUT_ELEMS (BB*SS*HH)       // 3145728
#define ATTN_ELEMS ((size_t)BB*NH*SS*SS) // 100663296
#define NEGV (-1e32f)

__device__ float g_qh[BB*NH*SS*DD];
__device__ float g_kh[BB*NH*SS*DD];
__device__ float g_vh[BB*NH*SS*DD];
__device__ float g_ctx[BB*SS*HH];
__device__ float g_linv[BH*SS];
__device__ float g_attn_scratch[BB*NH*SS*SS];

typedef wmma::fragment<wmma::matrix_a, 16, 16, 8, wmma::precision::tf32, wmma::row_major> FragA;
typedef wmma::fragment<wmma::matrix_b, 16, 16, 8, wmma::precision::tf32, wmma::col_major> FragBc;
typedef wmma::fragment<wmma::matrix_b, 16, 16, 8, wmma::precision::tf32, wmma::row_major> FragBr;
typedef wmma::fragment<wmma::accumulator, 16, 16, 8, float> FragC;

#define LDS 36          // proj slab stride (32 + 4)
#define SLAB 32
#define NSLAB (HH/SLAB) // 24
#define LDP 68          // 64 + 4
#define LDQ 132         // 128 + 4

#define CVT4(t4) do { \
    t4.x = wmma::__float_to_tf32(t4.x); t4.y = wmma::__float_to_tf32(t4.y); \
    t4.z = wmma::__float_to_tf32(t4.z); t4.w = wmma::__float_to_tf32(t4.w); } while(0)

// ============================================================
// GEMM mainloop: C(128x128) = X(128xK) @ W(128xK)^T, tf32, dbuf.
// 256 threads, 8 warps: wm=(w&1)*64, wn=(w>>1)*32. acc[4][2].
// ============================================================
__device__ __forceinline__ void gemm_mainloop(const float* __restrict__ X,
                                              const float* __restrict__ W,
                                              float* As, float* Bs,
                                              int m0, int n0, int tid,
                                              int wm, int wn, FragC acc[4][2]) {
    const int r = tid >> 1;
    const int c0 = (tid & 1) * 16;
    const float* xp = X + (size_t)(m0 + r) * HH + c0;
    const float* wp = W + (size_t)(n0 + r) * HH + c0;

    float4 xa[4], wb[4];
    #pragma unroll
    for (int i = 0; i < 4; i++) { xa[i] = *(const float4*)(xp + i * 4); wb[i] = *(const float4*)(wp + i * 4); }
    #pragma unroll
    for (int i = 0; i < 4; i++) {
        CVT4(xa[i]); *(float4*)&As[r * LDS + c0 + i * 4] = xa[i];
        CVT4(wb[i]); *(float4*)&Bs[r * LDS + c0 + i * 4] = wb[i];
    }
    __syncthreads();

    int buf = 0;
    for (int s = 0; s < NSLAB; s++) {
        if (s + 1 < NSLAB) {
            const float* xq = xp + (s + 1) * SLAB;
            const float* wq = wp + (s + 1) * SLAB;
            #pragma unroll
            for (int i = 0; i < 4; i++) { xa[i] = *(const float4*)(xq + i * 4); wb[i] = *(const float4*)(wq + i * 4); }
        }
        float* A = As + buf * 128 * LDS;
        float* B = Bs + buf * 128 * LDS;
        #pragma unroll
        for (int kk = 0; kk < 4; kk++) {
            FragA a[4]; FragBc b[2];
            #pragma unroll
            for (int i = 0; i < 4; i++) wmma::load_matrix_sync(a[i], &A[(wm + i * 16) * LDS + kk * 8], LDS);
            #pragma unroll
            for (int j = 0; j < 2; j++) wmma::load_matrix_sync(b[j], &B[(wn + j * 16) * LDS + kk * 8], LDS);
            #pragma unroll
            for (int i = 0; i < 4; i++)
                #pragma unroll
                for (int j = 0; j < 2; j++) wmma::mma_sync(acc[i][j], a[i], b[j], acc[i][j]);
        }
        if (s + 1 < NSLAB) {
            float* A2 = As + (buf ^ 1) * 128 * LDS;
            float* B2 = Bs + (buf ^ 1) * 128 * LDS;
            #pragma unroll
            for (int i = 0; i < 4; i++) {
                CVT4(xa[i]); *(float4*)&A2[r * LDS + c0 + i * 4] = xa[i];
                CVT4(wb[i]); *(float4*)&B2[r * LDS + c0 + i * 4] = wb[i];
            }
        }
        __syncthreads();
        buf ^= 1;
    }
}

// ============================================================
// Kernel 1: fused QKV projections, head-split output.
// ============================================================
__global__ void proj_qkv_kernel(const float* __restrict__ q,
                                const float* __restrict__ k,
                                const float* __restrict__ v,
                                const float* __restrict__ Wq, const float* __restrict__ bq,
                                const float* __restrict__ Wk, const float* __restrict__ bk,
                                const float* __restrict__ Wv, const float* __restrict__ bv) {
    const float* X; const float* W; const float* bias; float* Y;
    if (blockIdx.z == 0)      { X = q; W = Wq; bias = bq; Y = g_qh; }
    else if (blockIdx.z == 1) { X = k; W = Wk; bias = bk; Y = g_kh; }
    else                      { X = v; W = Wv; bias = bv; Y = g_vh; }

    extern __shared__ float sm[];
    float* As = sm;
    float* Bs = sm + 2 * 128 * LDS;
    float* Cs = sm;
    __shared__ float bias_s[128];

    const int tid = threadIdx.x;
    const int w = tid >> 5;
    const int m0 = blockIdx.y * 128, n0 = blockIdx.x * 128;
    const int wm = (w & 1) * 64, wn = (w >> 1) * 32;
    if (tid < 128) bias_s[tid] = bias[n0 + tid];

    FragC acc[4][2];
    #pragma unroll
    for (int i = 0; i < 4; i++)
        #pragma unroll
        for (int j = 0; j < 2; j++) wmma::fill_fragment(acc[i][j], 0.0f);

    gemm_mainloop(X, W, As, Bs, m0, n0, tid, wm, wn, acc);

    #pragma unroll
    for (int i = 0; i < 4; i++)
        #pragma unroll
        for (int j = 0; j < 2; j++)
            wmma::store_matrix_sync(&Cs[(wm + i * 16) * LDQ + wn + j * 16], acc[i][j], LDQ, wmma::mem_row_major);
    __syncthreads();

    {
        const int r = tid >> 1;
        const int c0 = (tid & 1) * 64;
        const int h = (n0 + c0) >> 6;
        const int m = m0 + r, b = m >> 11, s = m & 2047;
        float* dst = &Y[(((size_t)b * NH + h) * SS + s) * DD];
        #pragma unroll
        for (int t = 0; t < 16; t++) {
            float4 t4 = *(float4*)&Cs[r * LDQ + c0 + t * 4];
            t4.x += bias_s[c0 + t * 4];     t4.y += bias_s[c0 + t * 4 + 1];
            t4.z += bias_s[c0 + t * 4 + 2]; t4.w += bias_s[c0 + t * 4 + 3];
            *(float4*)&dst[t * 4] = t4;
        }
    }
}

// ============================================================
// Kernel 2: fused attention (no-max softmax, deferred norm).
// 512 threads, 128 Q rows, 128-col K/V chunks.
// ============================================================
__global__ void __launch_bounds__(512, 1)
fused_attn_kernel(const int* __restrict__ mask, float* __restrict__ attn) {
    extern __shared__ float sm[];
    float* Qs    = sm;                    // [128][LDP]
    float* Ks    = Qs + 128 * LDP;        // [128][LDP]
    float* Vs    = Ks + 128 * LDP;        // [128][LDP]
    float* ps    = Vs + 128 * LDP;        // [128][LDQ]
    float* biasv = ps + 128 * LDQ;        // [2048]

    const int tid = threadIdx.x;
    const int w = tid >> 5;
    const int bh = blockIdx.y;
    const int b = bh / NH, h = bh % NH;
    const int m0 = blockIdx.x * 128;

    const float* qh_head = g_qh + (size_t)bh * SS * DD + (size_t)m0 * DD;
    const float* kh_head = g_kh + (size_t)bh * SS * DD;
    const float* vh_head = g_vh + (size_t)bh * SS * DD;

    // load Q tile (tf32)
    {
        int r = tid >> 2, cc = (tid & 3) * 16;
        #pragma unroll
        for (int i = 0; i < 4; i++) {
            float4 t4 = *(const float4*)&qh_head[(size_t)r * DD + cc + i * 4];
            CVT4(t4);
            *(float4*)&Qs[r * LDP + cc + i * 4] = t4;
        }
    }
    #pragma unroll
    for (int i = 0; i < 4; i++) {
        int c = tid + i * 512;
        biasv[c] = mask[b * SS + c] ? NEGV : 0.0f;
    }
    __syncthreads();

    const int erow = tid >> 2, ec0 = (tid & 3) * 32;
    const int wmQ = (w & 3) * 32, wnQ = (w >> 2) * 32;
    const int wmA = (w & 3) * 32, wnA = (w >> 2) * 16;
    float l_run = 0.0f;

    FragC accv[2];
    wmma::fill_fragment(accv[0], 0.0f);
    wmma::fill_fragment(accv[1], 0.0f);

    float* arow = attn + ((size_t)bh * SS + m0 + erow) * SS;

    for (int c0 = 0; c0 < SS; c0 += 128) {
        // ---- load K,V chunk (tf32) ----
        {
            int r = tid >> 2, cc = (tid & 3) * 16;
            const float* ksrc = kh_head + (size_t)(c0 + r) * DD + cc;
            const float* vsrc = vh_head + (size_t)(c0 + r) * DD + cc;
            #pragma unroll
            for (int i = 0; i < 4; i++) {
                float4 t4 = *(const float4*)(ksrc + i * 4);
                CVT4(t4); *(float4*)&Ks[r * LDP + cc + i * 4] = t4;
                float4 u4 = *(const float4*)(vsrc + i * 4);
                CVT4(u4); *(float4*)&Vs[r * LDP + cc + i * 4] = u4;
            }
        }
        __syncthreads();

        // ---- S = Q @ K^T (128x128) ----
        {
            FragC sa[2][2];
            #pragma unroll
            for (int i = 0; i < 2; i++)
                #pragma unroll
                for (int j = 0; j < 2; j++) wmma::fill_fragment(sa[i][j], 0.0f);
            #pragma unroll
            for (int kk = 0; kk < 8; kk++) {
                FragA a0, a1; FragBc b0, b1;
                wmma::load_matrix_sync(a0, &Qs[(wmQ +  0) * LDP + kk * 8], LDP);
                wmma::load_matrix_sync(a1, &Qs[(wmQ + 16) * LDP + kk * 8], LDP);
                wmma::load_matrix_sync(b0, &Ks[(wnQ +  0) * LDP + kk * 8], LDP);
                wmma::load_matrix_sync(b1, &Ks[(wnQ + 16) * LDP + kk * 8], LDP);
                wmma::mma_sync(sa[0][0], a0, b0, sa[0][0]);
                wmma::mma_sync(sa[0][1], a0, b1, sa[0][1]);
                wmma::mma_sync(sa[1][0], a1, b0, sa[1][0]);
                wmma::mma_sync(sa[1][1], a1, b1, sa[1][1]);
            }
            #pragma unroll
            for (int i = 0; i < 2; i++)
                #pragma unroll
                for (int j = 0; j < 2; j++)
                    wmma::store_matrix_sync(&ps[(wmQ + i * 16) * LDQ + wnQ + j * 16], sa[i][j], LDQ, wmma::mem_row_major);
        }
        __syncthreads();

        // ---- p_u = exp(0.125*s + bias); write attn; tf32 back ----
        {
            float lsum = 0.0f;
            #pragma unroll
            for (int i = 0; i < 8; i++) {
                int c = ec0 + i * 4;
                float4 t4 = *(float4*)&ps[erow * LDQ + c];
                float4 b4 = *(const float4*)&biasv[c0 + c];
                float4 p4;
                p4.x = __expf(fmaf(t4.x, 0.125f, b4.x));
                p4.y = __expf(fmaf(t4.y, 0.125f, b4.y));
                p4.z = __expf(fmaf(t4.z, 0.125f, b4.z));
                p4.w = __expf(fmaf(t4.w, 0.125f, b4.w));
                lsum += p4.x + p4.y + p4.z + p4.w;
                *(float4*)&arow[c0 + c] = p4;
                CVT4(p4);
                *(float4*)&ps[erow * LDQ + c] = p4;
            }
            l_run += lsum;
        }
        __syncthreads();

        // ---- AV accumulate: accv += P(128x128) @ V(128x64) ----
        #pragma unroll
        for (int kk = 0; kk < 16; kk++) {
            FragA a0, a1; FragBr bf;
            wmma::load_matrix_sync(a0, &ps[(wmA +  0) * LDQ + kk * 8], LDQ);
            wmma::load_matrix_sync(a1, &ps[(wmA + 16) * LDQ + kk * 8], LDQ);
            wmma::load_matrix_sync(bf, &Vs[(kk * 8) * LDP + wnA], LDP);
            wmma::mma_sync(accv[0], a0, bf, accv[0]);
            wmma::mma_sync(accv[1], a1, bf, accv[1]);
        }
        __syncthreads();
    }

    // finalize row sum across the 4 threads of this row
    l_run += __shfl_xor_sync(0xFFFFFFFFu, l_run, 1);
    l_run += __shfl_xor_sync(0xFFFFFFFFu, l_run, 2);
    float inv_l = 1.0f / l_run;
    if ((tid & 3) == 0) g_linv[bh * SS + m0 + erow] = inv_l;

    // store accv, normalize, write ctx
    wmma::store_matrix_sync(&ps[(wmA +  0) * LDQ + wnA], accv[0], LDQ, wmma::mem_row_major);
    wmma::store_matrix_sync(&ps[(wmA + 16) * LDQ + wnA], accv[1], LDQ, wmma::mem_row_major);
    __syncthreads();
    {
        int cw = (tid & 3) * 16;
        float* dst = &g_ctx[((size_t)(b * SS + m0 + erow)) * HH + h * 64 + cw];
        #pragma unroll
        for (int i = 0; i < 4; i++) {
            float4 t4 = *(float4*)&ps[erow * LDQ + cw + i * 4];
            t4.x *= inv_l; t4.y *= inv_l; t4.z *= inv_l; t4.w *= inv_l;
            *(float4*)&dst[i * 4] = t4;
        }
    }
}

// ============================================================
// Kernel 3: attn rescale (row-wise 1/sum).
// ============================================================
__global__ void __launch_bounds__(256)
attn_scale_kernel(float* __restrict__ attn) {
    const int row = blockIdx.x;
    const float inv = g_linv[row];
    float* p = attn + (size_t)row * SS;
    const int t = threadIdx.x;
    #pragma unroll
    for (int i = 0; i < 2; i++) {
        int c = (t + i * 256) * 4;
        float4 v4 = *(float4*)&p[c];
        v4.x *= inv; v4.y *= inv; v4.z *= inv; v4.w *= inv;
        *(float4*)&p[c] = v4;
    }
}

// ============================================================
// Kernel 4: out = ctx @ Wm^T + bm.
// ============================================================
__global__ void out_proj_kernel(const float* __restrict__ Wm,
                                const float* __restrict__ bm,
                                float* __restrict__ out) {
    extern __shared__ float sm[];
    float* As = sm;
    float* Bs = sm + 2 * 128 * LDS;
    float* Cs = sm;
    __shared__ float bias_s[128];

    const int tid = threadIdx.x;
    const int w = tid >> 5;
    const int m0 = blockIdx.y * 128, n0 = blockIdx.x * 128;
    const int wm = (w & 1) * 64, wn = (w >> 1) * 32;
    if (tid < 128) bias_s[tid] = bm[n0 + tid];

    FragC acc[4][2];
    #pragma unroll
    for (int i = 0; i < 4; i++)
        #pragma unroll
        for (int j = 0; j < 2; j++) wmma::fill_fragment(acc[i][j], 0.0f);

    gemm_mainloop(g_ctx, Wm, As, Bs, m0, n0, tid, wm, wn, acc);

    #pragma unroll
    for (int i = 0; i < 4; i++)
        #pragma unroll
        for (int j = 0; j < 2; j++)
            wmma::store_matrix_sync(&Cs[(wm + i * 16) * LDQ + wn + j * 16], acc[i][j], LDQ, wmma::mem_row_major);
    __syncthreads();

    {
        const int r = tid >> 1;
        const int c0 = (tid & 1) * 64;
        float* dst = &out[(size_t)(m0 + r) * HH + n0 + c0];
        #pragma unroll
        for (int t = 0; t < 16; t++) {
            float4 t4 = *(float4*)&Cs[r * LDQ + c0 + t * 4];
            t4.x += bias_s[c0 + t * 4];     t4.y += bias_s[c0 + t * 4 + 1];
            t4.z += bias_s[c0 + t * 4 + 2]; t4.w += bias_s[c0 + t * 4 + 3];
            *(float4*)&dst[t * 4] = t4;
        }
    }
}

// ============================================================
// Host launcher
// ============================================================
extern "C" void kernel_launch(void* const* d_in, const int* in_sizes, int n_in,
                              void* d_out, int out_size) {
    const float* v    = (const float*)d_in[0];
    const float* k    = (const float*)d_in[1];
    const float* q    = (const float*)d_in[2];
    const int*   mask = (const int*)  d_in[3];
    const float* Wv   = (const float*)d_in[4];
    const float* bv   = (const float*)d_in[5];
    const float* Wk   = (const float*)d_in[6];
    const float* bk   = (const float*)d_in[7];
    const float* Wq   = (const float*)d_in[8];
    const float* bq   = (const float*)d_in[9];
    const float* Wm   = (const float*)d_in[10];
    const float* bm   = (const float*)d_in[11];
    float* out = (float*)d_out;

    float* attn;
    if ((size_t)out_size >= (size_t)OUT_ELEMS + ATTN_ELEMS) {
        attn = out + OUT_ELEMS;
    } else {
        void* p = nullptr;
        cudaGetSymbolAddress(&p, g_attn_scratch);
        attn = (float*)p;
    }

    const int SMEM_GEMM = 4 * 128 * LDS * 4;                                    // 73728
    const int SMEM_FA   = (3 * 128 * LDP + 128 * LDQ + 2048) * 4;               // 180224
    static int smem_set = 0;
    if (!smem_set) {
        cudaFuncSetAttribute(proj_qkv_kernel, cudaFuncAttributeMaxDynamicSharedMemorySize, SMEM_GEMM);
        cudaFuncSetAttribute(out_proj_kernel, cudaFuncAttributeMaxDynamicSharedMemorySize, SMEM_GEMM);
        cudaFuncSetAttribute(fused_attn_kernel, cudaFuncAttributeMaxDynamicSharedMemorySize, SMEM_FA);
        smem_set = 1;
    }

    proj_qkv_kernel<<<dim3(HH / 128, M_PROJ / 128, 3), 256, SMEM_GEMM>>>(q, k, v, Wq, bq, Wk, bk, Wv, bv);
    fused_attn_kernel<<<dim3(SS / 128, BH), 512, SMEM_FA>>>(mask, attn);
    attn_scale_kernel<<<BH * SS, 256>>>(attn);
    out_proj_kernel<<<dim3(HH / 128, M_PROJ / 128, 1), 256, SMEM_GEMM>>>(Wm, bm, out);
}